// round 1
// baseline (speedup 1.0000x reference)
#include <cuda_runtime.h>

#define FULLMASK 0xffffffffu

static __device__ __forceinline__ float fixv(float p) {
    return (p == -1.0f) ? 0.0f : p;
}

// One CTA per batch image. 512 threads: thread t owns image row (t>>3),
// col blocks [4*(t&7) .. +3] and [4*(t&7)+32 .. +35].
__global__ __launch_bounds__(512, 1)
void prop_kernel(const float* __restrict__ X,
                 const float* __restrict__ pred,
                 const float* __restrict__ w,
                 const float* __restrict__ a,
                 const float* __restrict__ bias,
                 const float* __restrict__ scalar,
                 float* __restrict__ out)
{
    constexpr int NS = 64;          // image side
    constexpr int HH = NS * NS;     // 4096 pixels
    constexpr int SROWS = 66;       // +2 halo rows
    constexpr int ITERS = 12;

    __shared__ float U[2][SROWS * NS];

    const int b   = blockIdx.x;
    const int t   = threadIdx.x;
    const int row = t >> 3;         // 0..63
    const int cb  = t & 7;          // col block within row
    const int l   = t & 31;         // lane
    const int lb  = l & 24;         // lane-group base (8-lane row group)

    // Zero halo rows (rows 0 and 65) in both buffers; never written again.
    if (t < NS) {
        U[0][t] = 0.f;            U[1][t] = 0.f;
        U[0][65 * NS + t] = 0.f;  U[1][65 * NS + t] = 0.f;
    }

    const float s = scalar[0];
    const int c0 = cb * 4;
    const int c1 = c0 + 32;
    const int gbase = b * HH + row * NS;
    const int pbase = row * NS;

    // Global loads (all 16B aligned)
    float4 p0  = *(const float4*)(pred + gbase + c0);
    float4 p1  = *(const float4*)(pred + gbase + c1);
    float4 x0  = *(const float4*)(X    + gbase + c0);
    float4 x1  = *(const float4*)(X    + gbase + c1);
    float4 w0  = *(const float4*)(w    + pbase + c0);
    float4 w1  = *(const float4*)(w    + pbase + c1);
    float4 a0  = *(const float4*)(a    + pbase + c0);
    float4 a1  = *(const float4*)(a    + pbase + c1);
    float4 bb0 = *(const float4*)(bias + pbase + c0);
    float4 bb1 = *(const float4*)(bias + pbase + c1);

    // cs = s * (u_fix + bias + a*X)   (loop-invariant, in registers)
    float4 cs0, cs1, sw0, sw1;
    cs0.x = s * (fixv(p0.x) + bb0.x + a0.x * x0.x);
    cs0.y = s * (fixv(p0.y) + bb0.y + a0.y * x0.y);
    cs0.z = s * (fixv(p0.z) + bb0.z + a0.z * x0.z);
    cs0.w = s * (fixv(p0.w) + bb0.w + a0.w * x0.w);
    cs1.x = s * (fixv(p1.x) + bb1.x + a1.x * x1.x);
    cs1.y = s * (fixv(p1.y) + bb1.y + a1.y * x1.y);
    cs1.z = s * (fixv(p1.z) + bb1.z + a1.z * x1.z);
    cs1.w = s * (fixv(p1.w) + bb1.w + a1.w * x1.w);
    sw0.x = s * w0.x;  sw0.y = s * w0.y;  sw0.z = s * w0.z;  sw0.w = s * w0.w;
    sw1.x = s * w1.x;  sw1.y = s * w1.y;  sw1.z = s * w1.z;  sw1.w = s * w1.w;

    // u_0 = pred
    const int sbase = (row + 1) * NS;
    *(float4*)&U[0][sbase + c0] = p0;
    *(float4*)&U[0][sbase + c1] = p1;
    __syncthreads();

    float4 r0 = p0, r1 = p1;
    int cur = 0;

    #pragma unroll 1
    for (int it = 0; it < ITERS; ++it) {
        const float* __restrict__ Uc = U[cur];
        float*       __restrict__ Un = U[cur ^ 1];

        float4 sA = make_float4(0.f, 0.f, 0.f, 0.f);
        float4 sB = make_float4(0.f, 0.f, 0.f, 0.f);

        #pragma unroll
        for (int dr = 0; dr < 3; ++dr) {
            // rows (row-1, row, row+1) => halo indices (row, row+1, row+2)
            const float4 ua = *(const float4*)&Uc[(row + dr) * NS + c0];
            const float4 ub = *(const float4*)&Uc[(row + dr) * NS + c1];

            // horizontal edges via intra-row-group shuffles
            float aL  = __shfl_up_sync  (FULLMASK, ua.w, 1);
            float aRn = __shfl_down_sync(FULLMASK, ua.x, 1);
            float bFx = __shfl_sync     (FULLMASK, ub.x, lb);      // group's cb==0 lane
            float bLn = __shfl_up_sync  (FULLMASK, ub.w, 1);
            float aLw = __shfl_sync     (FULLMASK, ua.w, lb | 7);  // group's cb==7 lane
            float bRn = __shfl_down_sync(FULLMASK, ub.x, 1);

            if (cb == 0) aL = 0.f;                  // col -1 halo
            float aR = (cb == 7) ? bFx : aRn;       // col 32 seam
            float bL = (cb == 0) ? aLw : bLn;       // col 31 seam
            float bR = (cb == 7) ? 0.f : bRn;       // col 64 halo

            sA.x += aL   + ua.x + ua.y;
            sA.y += ua.x + ua.y + ua.z;
            sA.z += ua.y + ua.z + ua.w;
            sA.w += ua.z + ua.w + aR;
            sB.x += bL   + ub.x + ub.y;
            sB.y += ub.x + ub.y + ub.z;
            sB.z += ub.y + ub.z + ub.w;
            sB.w += ub.z + ub.w + bR;
        }

        // u_new = tanh(cs + sw * boxsum)
        r0.x = tanhf(fmaf(sw0.x, sA.x, cs0.x));
        r0.y = tanhf(fmaf(sw0.y, sA.y, cs0.y));
        r0.z = tanhf(fmaf(sw0.z, sA.z, cs0.z));
        r0.w = tanhf(fmaf(sw0.w, sA.w, cs0.w));
        r1.x = tanhf(fmaf(sw1.x, sB.x, cs1.x));
        r1.y = tanhf(fmaf(sw1.y, sB.y, cs1.y));
        r1.z = tanhf(fmaf(sw1.z, sB.z, cs1.z));
        r1.w = tanhf(fmaf(sw1.w, sB.w, cs1.w));

        *(float4*)&Un[sbase + c0] = r0;
        *(float4*)&Un[sbase + c1] = r1;
        __syncthreads();
        cur ^= 1;
    }

    // final iterate still lives in registers
    *(float4*)(out + gbase + c0) = r0;
    *(float4*)(out + gbase + c1) = r1;
}

extern "C" void kernel_launch(void* const* d_in, const int* in_sizes, int n_in,
                              void* d_out, int out_size) {
    const float* X      = (const float*)d_in[0];
    const float* pred   = (const float*)d_in[1];
    const float* w      = (const float*)d_in[2];
    const float* a      = (const float*)d_in[3];
    const float* bias   = (const float*)d_in[4];
    const float* scalar = (const float*)d_in[5];
    float* out = (float*)d_out;

    const int B = in_sizes[0] / 4096;   // batch = 128
    prop_kernel<<<B, 512>>>(X, pred, w, a, bias, scalar, out);
}

// round 2
// speedup vs baseline: 1.1157x; 1.1157x over previous
#include <cuda_runtime.h>

#define FULLMASK 0xffffffffu

static __device__ __forceinline__ float fixv(float p) {
    return (p == -1.0f) ? 0.0f : p;
}

static __device__ __forceinline__ float tanh_fast(float x) {
    float y;
    asm("tanh.approx.f32 %0, %1;" : "=f"(y) : "f"(x));
    return y;
}

// One CTA per batch image. 1024 threads: thread t owns image row (t>>4),
// cols [4*(t&15) .. 4*(t&15)+3]. 16 lanes span one image row, so one warp
// covers exactly 2 rows; horizontal neighbors are lane±1 (image-edge lanes
// are masked, so the cross-row shuffle at lane 15|16 is harmless).
__global__ __launch_bounds__(1024, 1)
void prop_kernel(const float* __restrict__ X,
                 const float* __restrict__ pred,
                 const float* __restrict__ w,
                 const float* __restrict__ a,
                 const float* __restrict__ bias,
                 const float* __restrict__ scalar,
                 float* __restrict__ out)
{
    constexpr int NS = 64;          // image side
    constexpr int HH = NS * NS;     // 4096 pixels
    constexpr int SROWS = 66;       // +2 halo rows
    constexpr int ITERS = 12;

    __shared__ float U[2][SROWS * NS];

    const int b   = blockIdx.x;
    const int t   = threadIdx.x;
    const int row = t >> 4;         // 0..63
    const int cb  = t & 15;         // col block within row (4 cols each)

    // Zero halo rows (rows 0 and 65) in both buffers; never written again.
    if (t < NS) {
        U[0][t] = 0.f;            U[1][t] = 0.f;
        U[0][65 * NS + t] = 0.f;  U[1][65 * NS + t] = 0.f;
    }

    const float s = scalar[0];
    const int c0 = cb * 4;
    const int gbase = b * HH + row * NS + c0;
    const int pbase = row * NS + c0;

    // Global loads (all 16B aligned, coalesced)
    float4 p0  = *(const float4*)(pred + gbase);
    float4 x0  = *(const float4*)(X    + gbase);
    float4 w0  = *(const float4*)(w    + pbase);
    float4 a0  = *(const float4*)(a    + pbase);
    float4 bb0 = *(const float4*)(bias + pbase);

    // cs = s * (u_fix + bias + a*X)   (loop-invariant, registers)
    float4 cs0, sw0;
    cs0.x = s * (fixv(p0.x) + bb0.x + a0.x * x0.x);
    cs0.y = s * (fixv(p0.y) + bb0.y + a0.y * x0.y);
    cs0.z = s * (fixv(p0.z) + bb0.z + a0.z * x0.z);
    cs0.w = s * (fixv(p0.w) + bb0.w + a0.w * x0.w);
    sw0.x = s * w0.x;  sw0.y = s * w0.y;  sw0.z = s * w0.z;  sw0.w = s * w0.w;

    // u_0 = pred
    const int sidx = (row + 1) * NS + c0;
    *(float4*)&U[0][sidx] = p0;
    __syncthreads();

    float4 r0 = p0;
    int cur = 0;

    #pragma unroll 1
    for (int it = 0; it < ITERS; ++it) {
        const float* __restrict__ Uc = U[cur];
        float*       __restrict__ Un = U[cur ^ 1];

        float4 sA = make_float4(0.f, 0.f, 0.f, 0.f);

        #pragma unroll
        for (int dr = 0; dr < 3; ++dr) {
            // rows (row-1, row, row+1) => halo indices (row, row+1, row+2)
            const float4 ua = *(const float4*)&Uc[(row + dr) * NS + c0];

            // horizontal edges via intra-warp shuffles (lane±1)
            float aL = __shfl_up_sync  (FULLMASK, ua.w, 1);
            float aR = __shfl_down_sync(FULLMASK, ua.x, 1);
            if (cb == 0)  aL = 0.f;     // col -1 halo (also kills cross-row leak)
            if (cb == 15) aR = 0.f;     // col 64 halo

            sA.x += aL   + ua.x + ua.y;
            sA.y += ua.x + ua.y + ua.z;
            sA.z += ua.y + ua.z + ua.w;
            sA.w += ua.z + ua.w + aR;
        }

        // u_new = tanh(cs + sw * boxsum)
        r0.x = tanh_fast(fmaf(sw0.x, sA.x, cs0.x));
        r0.y = tanh_fast(fmaf(sw0.y, sA.y, cs0.y));
        r0.z = tanh_fast(fmaf(sw0.z, sA.z, cs0.z));
        r0.w = tanh_fast(fmaf(sw0.w, sA.w, cs0.w));

        *(float4*)&Un[sidx] = r0;
        __syncthreads();
        cur ^= 1;
    }

    // final iterate still lives in registers
    *(float4*)(out + gbase) = r0;
}

extern "C" void kernel_launch(void* const* d_in, const int* in_sizes, int n_in,
                              void* d_out, int out_size) {
    const float* X      = (const float*)d_in[0];
    const float* pred   = (const float*)d_in[1];
    const float* w      = (const float*)d_in[2];
    const float* a      = (const float*)d_in[3];
    const float* bias   = (const float*)d_in[4];
    const float* scalar = (const float*)d_in[5];
    float* out = (float*)d_out;

    const int B = in_sizes[0] / 4096;   // batch = 128
    prop_kernel<<<B, 1024>>>(X, pred, w, a, bias, scalar, out);
}

// round 3
// speedup vs baseline: 1.3862x; 1.2425x over previous
#include <cuda_runtime.h>

#define FULLMASK 0xffffffffu

static __device__ __forceinline__ float fixv(float p) {
    return (p == -1.0f) ? 0.0f : p;
}

static __device__ __forceinline__ float tanh_fast(float x) {
    float y;
    asm("tanh.approx.f32 %0, %1;" : "=f"(y) : "f"(x));
    return y;
}

// One CTA per batch image, 1024 threads, 4 pixels/thread.
// Thread t owns image row (t>>4), cols [4*(t&15)..+3].
// Warp w covers rows 2w (lanes 0-15) and 2w+1 (lanes 16-31).
//
// Separable stencil: per iteration each thread computes the horizontal 3-sum
// hx of its own row (registers + 2 intra-row shuffles), publishes hx to smem,
// gets the in-warp vertical neighbor's h via shfl_xor(16), and the out-of-warp
// neighbor via ONE LDS.128. u itself never goes to shared memory.
__global__ __launch_bounds__(1024, 1)
void prop_kernel(const float* __restrict__ X,
                 const float* __restrict__ pred,
                 const float* __restrict__ w,
                 const float* __restrict__ a,
                 const float* __restrict__ bias,
                 const float* __restrict__ scalar,
                 float* __restrict__ out)
{
    constexpr int NS = 64;          // image side
    constexpr int HH = NS * NS;     // 4096 pixels
    constexpr int SROWS = 66;       // +2 zero halo rows
    constexpr int ITERS = 12;

    __shared__ float Hs[2][SROWS * NS];   // horizontal 3-sums, double buffered

    const int b   = blockIdx.x;
    const int t   = threadIdx.x;
    const int row = t >> 4;         // 0..63
    const int cb  = t & 15;         // col block (4 cols each)

    // Zero halo rows (halo indices 0 and 65) in both buffers, once.
    if (t < NS) {
        Hs[0][t] = 0.f;            Hs[1][t] = 0.f;
        Hs[0][65 * NS + t] = 0.f;  Hs[1][65 * NS + t] = 0.f;
    }

    const float s = scalar[0];
    const int c0 = cb * 4;
    const int gbase = b * HH + row * NS + c0;
    const int pbase = row * NS + c0;

    // Global loads (16B aligned, coalesced)
    float4 p0  = *(const float4*)(pred + gbase);
    float4 x0  = *(const float4*)(X    + gbase);
    float4 w0  = *(const float4*)(w    + pbase);
    float4 a0  = *(const float4*)(a    + pbase);
    float4 bb0 = *(const float4*)(bias + pbase);

    // cs = s*(u_fix + bias + a*X), sw = s*w   (loop-invariant, registers)
    float4 cs0, sw0;
    cs0.x = s * (fixv(p0.x) + bb0.x + a0.x * x0.x);
    cs0.y = s * (fixv(p0.y) + bb0.y + a0.y * x0.y);
    cs0.z = s * (fixv(p0.z) + bb0.z + a0.z * x0.z);
    cs0.w = s * (fixv(p0.w) + bb0.w + a0.w * x0.w);
    sw0.x = s * w0.x;  sw0.y = s * w0.y;  sw0.z = s * w0.z;  sw0.w = s * w0.w;

    // smem addresses (halo coords: own row -> index row+1)
    const int sidx = (row + 1) * NS + c0;                    // store slot
    const int vidx = (row + ((t & 16) ? 2 : 0)) * NS + c0;   // out-of-warp vert neighbor

    float4 r0 = p0;      // u_0 = pred
    int cur = 0;

    #pragma unroll 1
    for (int it = 0; it < ITERS; ++it) {
        // --- horizontal 3-sum of own row (registers + 2 shuffles) ---
        float aL = __shfl_up_sync  (FULLMASK, r0.w, 1);
        float aR = __shfl_down_sync(FULLMASK, r0.x, 1);
        if (cb == 0)  aL = 0.f;     // image left edge (also kills half-warp leak)
        if (cb == 15) aR = 0.f;     // image right edge

        float4 hx;
        hx.x = aL   + r0.x + r0.y;
        hx.y = r0.x + r0.y + r0.z;
        hx.z = r0.y + r0.z + r0.w;
        hx.w = r0.z + r0.w + aR;

        // publish h, sync, gather vertical neighbors
        *(float4*)&Hs[cur][sidx] = hx;

        // in-warp vertical neighbor: other half-warp's row
        float4 hn;
        hn.x = __shfl_xor_sync(FULLMASK, hx.x, 16);
        hn.y = __shfl_xor_sync(FULLMASK, hx.y, 16);
        hn.z = __shfl_xor_sync(FULLMASK, hx.z, 16);
        hn.w = __shfl_xor_sync(FULLMASK, hx.w, 16);

        __syncthreads();

        // out-of-warp vertical neighbor via one LDS.128
        const float4 hf = *(const float4*)&Hs[cur][vidx];

        // u_new = tanh(cs + sw * (h_above + h_self + h_below))
        r0.x = tanh_fast(fmaf(sw0.x, hf.x + hx.x + hn.x, cs0.x));
        r0.y = tanh_fast(fmaf(sw0.y, hf.y + hx.y + hn.y, cs0.y));
        r0.z = tanh_fast(fmaf(sw0.z, hf.z + hx.z + hn.z, cs0.z));
        r0.w = tanh_fast(fmaf(sw0.w, hf.w + hx.w + hn.w, cs0.w));

        cur ^= 1;
    }

    *(float4*)(out + gbase) = r0;
}

extern "C" void kernel_launch(void* const* d_in, const int* in_sizes, int n_in,
                              void* d_out, int out_size) {
    const float* X      = (const float*)d_in[0];
    const float* pred   = (const float*)d_in[1];
    const float* w      = (const float*)d_in[2];
    const float* a      = (const float*)d_in[3];
    const float* bias   = (const float*)d_in[4];
    const float* scalar = (const float*)d_in[5];
    float* out = (float*)d_out;

    const int B = in_sizes[0] / 4096;   // batch = 128
    prop_kernel<<<B, 1024>>>(X, pred, w, a, bias, scalar, out);
}

// round 4
// speedup vs baseline: 1.4560x; 1.0503x over previous
#include <cuda_runtime.h>

#define FULLMASK 0xffffffffu

static __device__ __forceinline__ float fixv(float p) {
    return (p == -1.0f) ? 0.0f : p;
}

static __device__ __forceinline__ float tanh_fast(float x) {
    float y;
    asm("tanh.approx.f32 %0, %1;" : "=f"(y) : "f"(x));
    return y;
}

// One CTA per batch image, 1024 threads, 4 pixels/thread.
// Thread t owns image row (t>>4), cols [4*(t&15)..+3].
//
// Separable stencil: per iteration each thread computes the horizontal 3-sum
// hx of its own row (registers + 2 intra-row shuffles), publishes hx to smem,
// then after one barrier reads BOTH vertical neighbor h-rows with two LDS.128
// (uniform indices: halo rows `row` and `row+2` for every thread).
// u itself never touches shared memory.
__global__ __launch_bounds__(1024, 1)
void prop_kernel(const float* __restrict__ X,
                 const float* __restrict__ pred,
                 const float* __restrict__ w,
                 const float* __restrict__ a,
                 const float* __restrict__ bias,
                 const float* __restrict__ scalar,
                 float* __restrict__ out)
{
    constexpr int NS = 64;          // image side
    constexpr int HH = NS * NS;     // 4096 pixels
    constexpr int SROWS = 66;       // +2 zero halo rows
    constexpr int ITERS = 12;

    __shared__ float Hs[2][SROWS * NS];   // horizontal 3-sums, double buffered

    const int b   = blockIdx.x;
    const int t   = threadIdx.x;
    const int row = t >> 4;         // 0..63
    const int cb  = t & 15;         // col block (4 cols each)

    // Zero halo rows (halo indices 0 and 65) in both buffers, once.
    if (t < NS) {
        Hs[0][t] = 0.f;            Hs[1][t] = 0.f;
        Hs[0][65 * NS + t] = 0.f;  Hs[1][65 * NS + t] = 0.f;
    }

    const float s = scalar[0];
    const int c0 = cb * 4;
    const int gbase = b * HH + row * NS + c0;
    const int pbase = row * NS + c0;

    // Global loads (16B aligned, coalesced)
    float4 p0  = *(const float4*)(pred + gbase);
    float4 x0  = *(const float4*)(X    + gbase);
    float4 w0  = *(const float4*)(w    + pbase);
    float4 a0  = *(const float4*)(a    + pbase);
    float4 bb0 = *(const float4*)(bias + pbase);

    // cs = s*(u_fix + bias + a*X), sw = s*w   (loop-invariant, registers)
    float4 cs0, sw0;
    cs0.x = s * (fixv(p0.x) + bb0.x + a0.x * x0.x);
    cs0.y = s * (fixv(p0.y) + bb0.y + a0.y * x0.y);
    cs0.z = s * (fixv(p0.z) + bb0.z + a0.z * x0.z);
    cs0.w = s * (fixv(p0.w) + bb0.w + a0.w * x0.w);
    sw0.x = s * w0.x;  sw0.y = s * w0.y;  sw0.z = s * w0.z;  sw0.w = s * w0.w;

    // smem indices (halo coords: own row stores at row+1; vertical neighbor
    // h-rows are at halo rows `row` and `row+2` — valid for every thread).
    const int sidx = (row + 1) * NS + c0;
    const int vA   =  row      * NS + c0;
    const int vB   = (row + 2) * NS + c0;

    float4 r0 = p0;      // u_0 = pred

    #pragma unroll
    for (int it = 0; it < ITERS; ++it) {
        float* __restrict__ Hc = Hs[it & 1];

        // --- horizontal 3-sum of own row (registers + 2 shuffles) ---
        float aL = __shfl_up_sync  (FULLMASK, r0.w, 1);
        float aR = __shfl_down_sync(FULLMASK, r0.x, 1);
        if (cb == 0)  aL = 0.f;     // image left edge (kills half-warp leak too)
        if (cb == 15) aR = 0.f;     // image right edge

        float4 hx;
        hx.x = aL   + r0.x + r0.y;
        hx.y = r0.x + r0.y + r0.z;
        hx.z = r0.y + r0.z + r0.w;
        hx.w = r0.z + r0.w + aR;

        *(float4*)&Hc[sidx] = hx;
        __syncthreads();

        // both vertical neighbor h-rows from smem
        const float4 hu = *(const float4*)&Hc[vA];
        const float4 hd = *(const float4*)&Hc[vB];

        // u_new = tanh(cs + sw * (h_above + h_self + h_below))
        r0.x = tanh_fast(fmaf(sw0.x, hu.x + hx.x + hd.x, cs0.x));
        r0.y = tanh_fast(fmaf(sw0.y, hu.y + hx.y + hd.y, cs0.y));
        r0.z = tanh_fast(fmaf(sw0.z, hu.z + hx.z + hd.z, cs0.z));
        r0.w = tanh_fast(fmaf(sw0.w, hu.w + hx.w + hd.w, cs0.w));
    }

    *(float4*)(out + gbase) = r0;
}

extern "C" void kernel_launch(void* const* d_in, const int* in_sizes, int n_in,
                              void* d_out, int out_size) {
    const float* X      = (const float*)d_in[0];
    const float* pred   = (const float*)d_in[1];
    const float* w      = (const float*)d_in[2];
    const float* a      = (const float*)d_in[3];
    const float* bias   = (const float*)d_in[4];
    const float* scalar = (const float*)d_in[5];
    float* out = (float*)d_out;

    const int B = in_sizes[0] / 4096;   // batch = 128
    prop_kernel<<<B, 1024>>>(X, pred, w, a, bias, scalar, out);
}